// round 4
// baseline (speedup 1.0000x reference)
#include <cuda_runtime.h>
#include <cstring>

#define N_RAYS   8192
#define N_SAMP   256
#define HID      64
#define OUT_ROW  261   // 3 colors + depth + missed + 256 probs

__global__ void __launch_bounds__(N_SAMP)
volume_render_kernel(const float* __restrict__ ray_start,
                     const float* __restrict__ ray_dir,
                     const float* __restrict__ depth,
                     const float* __restrict__ dists,
                     const int*   __restrict__ sampled_idx,   // int32 (jax x64 disabled)
                     const float* __restrict__ W1,
                     const float* __restrict__ b1,
                     const float* __restrict__ w_sigma,
                     const float* __restrict__ W_rgb,
                     const float* __restrict__ W_dir,
                     const float* __restrict__ b_rgb,
                     float* __restrict__ out)
{
    __shared__ float2     sab[HID];    // per-ray (a_j, b_j)
    __shared__ ulonglong2 sw2[HID];    // .x = packed (w_sigma_j, W_rgb[j][0]); .y = packed (W_rgb[j][1], W_rgb[j][2])
    __shared__ float      sdc[3];      // per-ray dir projection + b_rgb
    __shared__ float      swsum[8];    // per-warp fe sums
    __shared__ float      soff[8];     // exclusive warp offsets
    __shared__ float      spart[8][5]; // per-warp reduction partials

    const int r = blockIdx.x;
    const int t = threadIdx.x;
    const int lane = t & 31;
    const int wid  = t >> 5;

    const float rs0 = ray_start[3*r+0], rs1 = ray_start[3*r+1], rs2 = ray_start[3*r+2];
    const float rd0 = ray_dir  [3*r+0], rd1 = ray_dir  [3*r+1], rd2 = ray_dir  [3*r+2];

    if (t < HID) {
        float w0 = W1[t], w1 = W1[HID + t], w2 = W1[2*HID + t];
        float a  = fmaf(rs2, w2, fmaf(rs1, w1, fmaf(rs0, w0, b1[t])));
        float b  = fmaf(rd2, w2, fmaf(rd1, w1, rd0 * w0));
        sab[t] = make_float2(a, b);
        float2 p0 = make_float2(w_sigma[t],   W_rgb[3*t+0]);
        float2 p1 = make_float2(W_rgb[3*t+1], W_rgb[3*t+2]);
        unsigned long long u0, u1;
        memcpy(&u0, &p0, 8);
        memcpy(&u1, &p1, 8);
        sw2[t] = make_ulonglong2(u0, u1);
    }
    if (t < 3) {
        sdc[t] = fmaf(rd2, W_dir[6+t], fmaf(rd1, W_dir[3+t], fmaf(rd0, W_dir[t], b_rgb[t])));
    }
    __syncthreads();

    const size_t si = (size_t)r * N_SAMP + t;
    const float td  = depth[si];
    const float dd  = dists[si];
    const bool mask = (sampled_idx[si] != -1);

    // Packed accumulators: acc01 = (sigma, c0), acc23 = (c1, c2)
    unsigned long long acc01 = 0ULL, acc23 = 0ULL;
    #pragma unroll
    for (int j = 0; j < HID; j++) {
        float2     ab = sab[j];
        ulonglong2 w  = sw2[j];
        float h = fmaxf(fmaf(td, ab.y, ab.x), 0.f);
        unsigned long long hh;
        asm("mov.b64 %0, {%1, %1};" : "=l"(hh) : "f"(h));
        asm("fma.rn.f32x2 %0, %1, %2, %0;" : "+l"(acc01) : "l"(hh), "l"(w.x));
        asm("fma.rn.f32x2 %0, %1, %2, %0;" : "+l"(acc23) : "l"(hh), "l"(w.y));
    }
    float sig, c0, c1, c2;
    asm("mov.b64 {%0, %1}, %2;" : "=f"(sig), "=f"(c0) : "l"(acc01));
    asm("mov.b64 {%0, %1}, %2;" : "=f"(c1),  "=f"(c2) : "l"(acc23));

    // free energy (masked), alpha
    float fe = mask ? fmaxf(sig, 0.f) * dd * 7.0f : 0.f;
    float av = 1.f - __expf(-fe);

    // rgb sigmoids
    float r0 = __fdividef(1.f, 1.f + __expf(-(c0 + sdc[0])));
    float r1 = __fdividef(1.f, 1.f + __expf(-(c1 + sdc[1])));
    float r2 = __fdividef(1.f, 1.f + __expf(-(c2 + sdc[2])));

    // ---- exclusive prefix sum of fe across 256 threads ----
    float v = fe;
    #pragma unroll
    for (int o = 1; o < 32; o <<= 1) {
        float n = __shfl_up_sync(0xffffffffu, v, o);
        if (lane >= o) v += n;
    }
    if (lane == 31) swsum[wid] = v;
    __syncthreads();
    if (t == 0) {
        float s = 0.f;
        #pragma unroll
        for (int w = 0; w < 8; w++) { soff[w] = s; s += swsum[w]; }
    }
    __syncthreads();
    float excl = (v - fe) + soff[wid];

    float T    = __expf(-excl);
    float prob = av * T;

    // ---- block reductions: sum prob, depth*prob, rgb*prob ----
    float s0 = prob, s1 = td * prob, s2 = r0 * prob, s3 = r1 * prob, s4 = r2 * prob;
    #pragma unroll
    for (int o = 16; o; o >>= 1) {
        s0 += __shfl_xor_sync(0xffffffffu, s0, o);
        s1 += __shfl_xor_sync(0xffffffffu, s1, o);
        s2 += __shfl_xor_sync(0xffffffffu, s2, o);
        s3 += __shfl_xor_sync(0xffffffffu, s3, o);
        s4 += __shfl_xor_sync(0xffffffffu, s4, o);
    }
    if (lane == 0) {
        spart[wid][0] = s0; spart[wid][1] = s1; spart[wid][2] = s2;
        spart[wid][3] = s3; spart[wid][4] = s4;
    }
    __syncthreads();

    float* orow = out + (size_t)r * OUT_ROW;
    orow[5 + t] = prob;

    if (t == 0) {
        float a0 = 0.f, a1 = 0.f, a2 = 0.f, a3 = 0.f, a4 = 0.f;
        #pragma unroll
        for (int w = 0; w < 8; w++) {
            a0 += spart[w][0]; a1 += spart[w][1]; a2 += spart[w][2];
            a3 += spart[w][3]; a4 += spart[w][4];
        }
        orow[0] = a2;        // color r
        orow[1] = a3;        // color g
        orow[2] = a4;        // color b
        orow[3] = a1;        // depth
        orow[4] = 1.f - a0;  // missed
    }
}

extern "C" void kernel_launch(void* const* d_in, const int* in_sizes, int n_in,
                              void* d_out, int out_size)
{
    const float* ray_start = (const float*)d_in[0];
    const float* ray_dir   = (const float*)d_in[1];
    const float* depth     = (const float*)d_in[2];
    const float* dists     = (const float*)d_in[3];
    const int*   sidx      = (const int*)d_in[4];
    const float* W1        = (const float*)d_in[5];
    const float* b1        = (const float*)d_in[6];
    const float* w_sigma   = (const float*)d_in[7];
    const float* W_rgb     = (const float*)d_in[8];
    const float* W_dir     = (const float*)d_in[9];
    const float* b_rgb     = (const float*)d_in[10];
    float* out = (float*)d_out;

    volume_render_kernel<<<N_RAYS, N_SAMP>>>(
        ray_start, ray_dir, depth, dists, sidx,
        W1, b1, w_sigma, W_rgb, W_dir, b_rgb, out);
}

// round 6
// speedup vs baseline: 1.3963x; 1.3963x over previous
#include <cuda_runtime.h>

#define N_RAYS   8192
#define N_SAMP   256
#define HID      64
#define OUT_ROW  261        // 3 colors + depth + missed + 256 probs
#define RPB      4          // rays per block
#define THREADS  256        // 64 threads per ray, 4 samples per thread

__device__ __forceinline__ unsigned long long pack2(float lo, float hi) {
    unsigned long long r;
    asm("mov.b64 %0, {%1, %2};" : "=l"(r) : "f"(lo), "f"(hi));
    return r;
}
__device__ __forceinline__ void unpack2(unsigned long long v, float& lo, float& hi) {
    asm("mov.b64 {%0, %1}, %2;" : "=f"(lo), "=f"(hi) : "l"(v));
}
#define FMA2(acc, x, y) asm("fma.rn.f32x2 %0, %1, %2, %0;" : "+l"(acc) : "l"(x), "l"(y))

__global__ void __launch_bounds__(THREADS)
volume_render_kernel(const float* __restrict__ ray_start,
                     const float* __restrict__ ray_dir,
                     const float* __restrict__ depth,
                     const float* __restrict__ dists,
                     const int*   __restrict__ sampled_idx,
                     const float* __restrict__ W1,
                     const float* __restrict__ b1,
                     const float* __restrict__ w_sigma,
                     const float* __restrict__ W_rgb,
                     const float* __restrict__ W_dir,
                     const float* __restrict__ b_rgb,
                     float* __restrict__ out)
{
    __shared__ unsigned long long sA[RPB][HID];   // (a,a) per ray
    __shared__ unsigned long long sB[RPB][HID];   // (b,b) per ray
    __shared__ unsigned long long sWs[HID];       // (wsig/2, wsig/2)
    __shared__ unsigned long long sW0[HID];       // (wr/2, wr/2)
    __shared__ unsigned long long sW1[HID];
    __shared__ unsigned long long sW2[HID];
    __shared__ float sdc[RPB][3];
    __shared__ float swsum[RPB][2];
    __shared__ float spart[RPB][2][5];

    const int t    = threadIdx.x;
    const int rl   = t >> 6;          // ray within block
    const int j    = t & 63;          // hidden unit (prologue) / thread-in-ray (main)
    const int lane = t & 31;
    const int wir  = (t >> 5) & 1;    // warp within ray
    const int r    = blockIdx.x * RPB + rl;

    const float rs0 = ray_start[3*r+0], rs1 = ray_start[3*r+1], rs2 = ray_start[3*r+2];
    const float rd0 = ray_dir  [3*r+0], rd1 = ray_dir  [3*r+1], rd2 = ray_dir  [3*r+2];

    // ---- prologue: per-ray affine coeffs + pre-splatted half-weights ----
    {
        float w0 = W1[j], w1 = W1[HID + j], w2 = W1[2*HID + j];
        float a  = fmaf(rs2, w2, fmaf(rs1, w1, fmaf(rs0, w0, b1[j])));
        float b  = fmaf(rd2, w2, fmaf(rd1, w1, rd0 * w0));
        sA[rl][j] = pack2(a, a);
        sB[rl][j] = pack2(b, b);
        if (rl == 0) {
            float ws = 0.5f * w_sigma[j];
            float q0 = 0.5f * W_rgb[3*j+0];
            float q1 = 0.5f * W_rgb[3*j+1];
            float q2 = 0.5f * W_rgb[3*j+2];
            sWs[j] = pack2(ws, ws);
            sW0[j] = pack2(q0, q0);
            sW1[j] = pack2(q1, q1);
            sW2[j] = pack2(q2, q2);
        }
        if (j < 3) {
            sdc[rl][j] = fmaf(rd2, W_dir[6+j], fmaf(rd1, W_dir[3+j], fmaf(rd0, W_dir[j], b_rgb[j])));
        }
    }
    __syncthreads();

    // ---- load 4 consecutive samples per thread ----
    const size_t si = (size_t)r * N_SAMP + 4 * j;
    const float4 d4 = *(const float4*)(depth + si);
    const float4 x4 = *(const float4*)(dists + si);
    const int4   i4 = *(const int4*)(sampled_idx + si);

    const unsigned long long td01 = pack2(d4.x, d4.y);
    const unsigned long long td23 = pack2(d4.z, d4.w);
    const unsigned long long ABSM = 0x7FFFFFFF7FFFFFFFULL;

    unsigned long long sg01 = 0, sg23 = 0;
    unsigned long long c0p01 = 0, c0p23 = 0;
    unsigned long long c1p01 = 0, c1p23 = 0;
    unsigned long long c2p01 = 0, c2p23 = 0;

    #pragma unroll
    for (int k = 0; k < HID; k++) {
        unsigned long long A = sA[rl][k], B = sB[rl][k];
        unsigned long long h01, h23;
        asm("fma.rn.f32x2 %0, %1, %2, %3;" : "=l"(h01) : "l"(td01), "l"(B), "l"(A));
        asm("fma.rn.f32x2 %0, %1, %2, %3;" : "=l"(h23) : "l"(td23), "l"(B), "l"(A));
        // packed ReLU: p = h + |h| = 2*max(h,0); compensated by half-weights
        unsigned long long p01, p23;
        unsigned long long m01 = h01 & ABSM, m23 = h23 & ABSM;
        asm("add.rn.f32x2 %0, %1, %2;" : "=l"(p01) : "l"(h01), "l"(m01));
        asm("add.rn.f32x2 %0, %1, %2;" : "=l"(p23) : "l"(h23), "l"(m23));
        unsigned long long ws = sWs[k], w0 = sW0[k], w1 = sW1[k], w2 = sW2[k];
        FMA2(sg01,  p01, ws); FMA2(sg23,  p23, ws);
        FMA2(c0p01, p01, w0); FMA2(c0p23, p23, w0);
        FMA2(c1p01, p01, w1); FMA2(c1p23, p23, w1);
        FMA2(c2p01, p01, w2); FMA2(c2p23, p23, w2);
    }

    float sg[4], c0[4], c1[4], c2[4];
    unpack2(sg01,  sg[0], sg[1]); unpack2(sg23,  sg[2], sg[3]);
    unpack2(c0p01, c0[0], c0[1]); unpack2(c0p23, c0[2], c0[3]);
    unpack2(c1p01, c1[0], c1[1]); unpack2(c1p23, c1[2], c1[3]);
    unpack2(c2p01, c2[0], c2[1]); unpack2(c2p23, c2[2], c2[3]);

    const float tdv[4] = {d4.x, d4.y, d4.z, d4.w};
    const float ddv[4] = {x4.x, x4.y, x4.z, x4.w};
    const int   mkv[4] = {i4.x != -1, i4.y != -1, i4.z != -1, i4.w != -1};

    // ---- free energy + local inclusive prefix ----
    float fe[4];
    #pragma unroll
    for (int k = 0; k < 4; k++)
        fe[k] = mkv[k] ? fmaxf(sg[k], 0.f) * ddv[k] * 7.0f : 0.f;

    const float l0 = fe[0];
    const float l1 = l0 + fe[1];
    const float l2 = l1 + fe[2];
    const float tsum = l2 + fe[3];

    // warp-inclusive scan of per-thread sums
    float v = tsum;
    #pragma unroll
    for (int o = 1; o < 32; o <<= 1) {
        float n = __shfl_up_sync(0xffffffffu, v, o);
        if (lane >= o) v += n;
    }
    if (lane == 31) swsum[rl][wir] = v;
    __syncthreads();
    const float off = (v - tsum) + (wir ? swsum[rl][0] : 0.f);

    const float ex[4] = {off, off + l0, off + l1, off + l2};

    // ---- probs + sigmoids + partial sums ----
    const float dc0 = sdc[rl][0], dc1 = sdc[rl][1], dc2 = sdc[rl][2];
    float prob[4], rr[4], gg[4], bb[4];
    #pragma unroll
    for (int k = 0; k < 4; k++) {
        float T  = __expf(-ex[k]);
        float av = 1.f - __expf(-fe[k]);
        prob[k] = av * T;
        rr[k] = __fdividef(1.f, 1.f + __expf(-(c0[k] + dc0)));
        gg[k] = __fdividef(1.f, 1.f + __expf(-(c1[k] + dc1)));
        bb[k] = __fdividef(1.f, 1.f + __expf(-(c2[k] + dc2)));
    }

    float s0 = 0.f, s1 = 0.f, s2 = 0.f, s3 = 0.f, s4 = 0.f;
    #pragma unroll
    for (int k = 0; k < 4; k++) {
        s0 += prob[k];
        s1 = fmaf(tdv[k], prob[k], s1);
        s2 = fmaf(rr[k],  prob[k], s2);
        s3 = fmaf(gg[k],  prob[k], s3);
        s4 = fmaf(bb[k],  prob[k], s4);
    }
    #pragma unroll
    for (int o = 16; o; o >>= 1) {
        s0 += __shfl_xor_sync(0xffffffffu, s0, o);
        s1 += __shfl_xor_sync(0xffffffffu, s1, o);
        s2 += __shfl_xor_sync(0xffffffffu, s2, o);
        s3 += __shfl_xor_sync(0xffffffffu, s3, o);
        s4 += __shfl_xor_sync(0xffffffffu, s4, o);
    }
    if (lane == 0) {
        spart[rl][wir][0] = s0; spart[rl][wir][1] = s1; spart[rl][wir][2] = s2;
        spart[rl][wir][3] = s3; spart[rl][wir][4] = s4;
    }

    float* orow = out + (size_t)r * OUT_ROW;
    #pragma unroll
    for (int k = 0; k < 4; k++)
        orow[5 + 4*j + k] = prob[k];

    __syncthreads();
    if (j == 0 && wir == 0) {
        float a0 = spart[rl][0][0] + spart[rl][1][0];
        float a1 = spart[rl][0][1] + spart[rl][1][1];
        float a2 = spart[rl][0][2] + spart[rl][1][2];
        float a3 = spart[rl][0][3] + spart[rl][1][3];
        float a4 = spart[rl][0][4] + spart[rl][1][4];
        orow[0] = a2;        // color r
        orow[1] = a3;        // color g
        orow[2] = a4;        // color b
        orow[3] = a1;        // depth
        orow[4] = 1.f - a0;  // missed
    }
}

extern "C" void kernel_launch(void* const* d_in, const int* in_sizes, int n_in,
                              void* d_out, int out_size)
{
    const float* ray_start = (const float*)d_in[0];
    const float* ray_dir   = (const float*)d_in[1];
    const float* depth     = (const float*)d_in[2];
    const float* dists     = (const float*)d_in[3];
    const int*   sidx      = (const int*)d_in[4];
    const float* W1        = (const float*)d_in[5];
    const float* b1        = (const float*)d_in[6];
    const float* w_sigma   = (const float*)d_in[7];
    const float* W_rgb     = (const float*)d_in[8];
    const float* W_dir     = (const float*)d_in[9];
    const float* b_rgb     = (const float*)d_in[10];
    float* out = (float*)d_out;

    volume_render_kernel<<<N_RAYS / RPB, THREADS>>>(
        ray_start, ray_dir, depth, dists, sidx,
        W1, b1, w_sigma, W_rgb, W_dir, b_rgb, out);
}

// round 7
// speedup vs baseline: 1.4413x; 1.0322x over previous
#include <cuda_runtime.h>

#define N_RAYS   8192
#define N_SAMP   256
#define HID      64
#define OUT_ROW  261        // 3 colors + depth + missed + 256 probs
#define RPB      8          // rays per block (one warp per ray)
#define THREADS  256

__device__ __forceinline__ unsigned long long pack2(float lo, float hi) {
    unsigned long long r;
    asm("mov.b64 %0, {%1, %2};" : "=l"(r) : "f"(lo), "f"(hi));
    return r;
}
__device__ __forceinline__ void unpack2(unsigned long long v, float& lo, float& hi) {
    asm("mov.b64 {%0, %1}, %2;" : "=f"(lo), "=f"(hi) : "l"(v));
}
#define FMA2(acc, x, y) asm("fma.rn.f32x2 %0, %1, %2, %0;" : "+l"(acc) : "l"(x), "l"(y))

__global__ void __launch_bounds__(THREADS, 2)
volume_render_kernel(const float* __restrict__ ray_start,
                     const float* __restrict__ ray_dir,
                     const float* __restrict__ depth,
                     const float* __restrict__ dists,
                     const int*   __restrict__ sampled_idx,
                     const float* __restrict__ W1,
                     const float* __restrict__ b1,
                     const float* __restrict__ w_sigma,
                     const float* __restrict__ W_rgb,
                     const float* __restrict__ W_dir,
                     const float* __restrict__ b_rgb,
                     float* __restrict__ out)
{
    __shared__ ulonglong2 sAB[RPB][HID];  // .x=(a,a) .y=(b,b) per ray
    __shared__ ulonglong2 sWa[HID];       // .x=(ws/2,ws/2) .y=(wr0/2,wr0/2)
    __shared__ ulonglong2 sWb[HID];       // .x=(wr1/2,..)   .y=(wr2/2,..)

    const int t    = threadIdx.x;
    const int rl   = t >> 5;      // ray slot in block == warp id
    const int lane = t & 31;
    const int r    = blockIdx.x * RPB + rl;

    const float rs0 = ray_start[3*r+0], rs1 = ray_start[3*r+1], rs2 = ray_start[3*r+2];
    const float rd0 = ray_dir  [3*r+0], rd1 = ray_dir  [3*r+1], rd2 = ray_dir  [3*r+2];

    // ---- prologue: per-ray affine coeffs (each warp fills its own ray) ----
    #pragma unroll
    for (int q = 0; q < 2; q++) {
        int jj = lane + 32*q;
        float w0 = W1[jj], w1 = W1[HID + jj], w2 = W1[2*HID + jj];
        float a  = fmaf(rs2, w2, fmaf(rs1, w1, fmaf(rs0, w0, b1[jj])));
        float b  = fmaf(rd2, w2, fmaf(rd1, w1, rd0 * w0));
        sAB[rl][jj] = make_ulonglong2(pack2(a, a), pack2(b, b));
    }
    if (t < HID) {
        float ws = 0.5f * w_sigma[t];
        float q0 = 0.5f * W_rgb[3*t+0];
        float q1 = 0.5f * W_rgb[3*t+1];
        float q2 = 0.5f * W_rgb[3*t+2];
        sWa[t] = make_ulonglong2(pack2(ws, ws), pack2(q0, q0));
        sWb[t] = make_ulonglong2(pack2(q1, q1), pack2(q2, q2));
    }
    __syncthreads();

    // ---- load 8 consecutive samples per thread ----
    const size_t si = (size_t)r * N_SAMP + lane * 8;
    const float4 dA = *(const float4*)(depth + si);
    const float4 dB = *(const float4*)(depth + si + 4);
    const float4 xA = *(const float4*)(dists + si);
    const float4 xB = *(const float4*)(dists + si + 4);
    const int4   iA = *(const int4*)(sampled_idx + si);
    const int4   iB = *(const int4*)(sampled_idx + si + 4);

    unsigned long long td[4];
    td[0] = pack2(dA.x, dA.y); td[1] = pack2(dA.z, dA.w);
    td[2] = pack2(dB.x, dB.y); td[3] = pack2(dB.z, dB.w);

    const unsigned long long ABSM = 0x7FFFFFFF7FFFFFFFULL;

    unsigned long long sg[4]  = {0,0,0,0};
    unsigned long long a0[4]  = {0,0,0,0};
    unsigned long long a1[4]  = {0,0,0,0};
    unsigned long long a2[4]  = {0,0,0,0};

    #pragma unroll 16
    for (int k = 0; k < HID; k++) {
        ulonglong2 ab = sAB[rl][k];   // broadcast LDS.128
        ulonglong2 wa = sWa[k];       // broadcast LDS.128
        ulonglong2 wb = sWb[k];       // broadcast LDS.128
        #pragma unroll
        for (int p = 0; p < 4; p++) {
            unsigned long long h, pr;
            asm("fma.rn.f32x2 %0, %1, %2, %3;" : "=l"(h) : "l"(td[p]), "l"(ab.y), "l"(ab.x));
            unsigned long long m = h & ABSM;             // |h| per half
            asm("add.rn.f32x2 %0, %1, %2;" : "=l"(pr) : "l"(h), "l"(m));  // 2*relu(h), exact
            FMA2(sg[p], pr, wa.x);
            FMA2(a0[p], pr, wa.y);
            FMA2(a1[p], pr, wb.x);
            FMA2(a2[p], pr, wb.y);
        }
    }

    float sgv[8], c0v[8], c1v[8], c2v[8];
    #pragma unroll
    for (int p = 0; p < 4; p++) {
        unpack2(sg[p], sgv[2*p], sgv[2*p+1]);
        unpack2(a0[p], c0v[2*p], c0v[2*p+1]);
        unpack2(a1[p], c1v[2*p], c1v[2*p+1]);
        unpack2(a2[p], c2v[2*p], c2v[2*p+1]);
    }

    const float tdv[8] = {dA.x,dA.y,dA.z,dA.w,dB.x,dB.y,dB.z,dB.w};
    const float ddv[8] = {xA.x,xA.y,xA.z,xA.w,xB.x,xB.y,xB.z,xB.w};
    const int   mkv[8] = {iA.x!=-1,iA.y!=-1,iA.z!=-1,iA.w!=-1,
                          iB.x!=-1,iB.y!=-1,iB.z!=-1,iB.w!=-1};

    // ---- free energy + exclusive prefix (warp == full ray) ----
    float fe[8], ex[8];
    float run = 0.f;
    #pragma unroll
    for (int k = 0; k < 8; k++) {
        fe[k] = mkv[k] ? fmaxf(sgv[k], 0.f) * ddv[k] * 7.0f : 0.f;
        ex[k] = run;
        run  += fe[k];
    }
    float v = run;
    #pragma unroll
    for (int o = 1; o < 32; o <<= 1) {
        float n = __shfl_up_sync(0xffffffffu, v, o);
        if (lane >= o) v += n;
    }
    const float excl = v - run;

    // ---- per-ray view-dir color offsets (registers, redundant per lane) ----
    const float dc0 = fmaf(rd2, W_dir[6], fmaf(rd1, W_dir[3], fmaf(rd0, W_dir[0], b_rgb[0])));
    const float dc1 = fmaf(rd2, W_dir[7], fmaf(rd1, W_dir[4], fmaf(rd0, W_dir[1], b_rgb[1])));
    const float dc2 = fmaf(rd2, W_dir[8], fmaf(rd1, W_dir[5], fmaf(rd0, W_dir[2], b_rgb[2])));

    float* orow = out + (size_t)r * OUT_ROW;

    float s0 = 0.f, s1 = 0.f, s2 = 0.f, s3 = 0.f, s4 = 0.f;
    #pragma unroll
    for (int k = 0; k < 8; k++) {
        float T    = __expf(-(excl + ex[k]));
        float av   = 1.f - __expf(-fe[k]);
        float prob = av * T;
        float rr = __fdividef(1.f, 1.f + __expf(-(c0v[k] + dc0)));
        float gg = __fdividef(1.f, 1.f + __expf(-(c1v[k] + dc1)));
        float bb = __fdividef(1.f, 1.f + __expf(-(c2v[k] + dc2)));
        orow[5 + 8*lane + k] = prob;
        s0 += prob;
        s1 = fmaf(tdv[k], prob, s1);
        s2 = fmaf(rr,     prob, s2);
        s3 = fmaf(gg,     prob, s3);
        s4 = fmaf(bb,     prob, s4);
    }
    #pragma unroll
    for (int o = 16; o; o >>= 1) {
        s0 += __shfl_xor_sync(0xffffffffu, s0, o);
        s1 += __shfl_xor_sync(0xffffffffu, s1, o);
        s2 += __shfl_xor_sync(0xffffffffu, s2, o);
        s3 += __shfl_xor_sync(0xffffffffu, s3, o);
        s4 += __shfl_xor_sync(0xffffffffu, s4, o);
    }
    if (lane == 0) {
        orow[0] = s2;        // color r
        orow[1] = s3;        // color g
        orow[2] = s4;        // color b
        orow[3] = s1;        // depth
        orow[4] = 1.f - s0;  // missed
    }
}

extern "C" void kernel_launch(void* const* d_in, const int* in_sizes, int n_in,
                              void* d_out, int out_size)
{
    const float* ray_start = (const float*)d_in[0];
    const float* ray_dir   = (const float*)d_in[1];
    const float* depth     = (const float*)d_in[2];
    const float* dists     = (const float*)d_in[3];
    const int*   sidx      = (const int*)d_in[4];
    const float* W1        = (const float*)d_in[5];
    const float* b1        = (const float*)d_in[6];
    const float* w_sigma   = (const float*)d_in[7];
    const float* W_rgb     = (const float*)d_in[8];
    const float* W_dir     = (const float*)d_in[9];
    const float* b_rgb     = (const float*)d_in[10];
    float* out = (float*)d_out;

    volume_render_kernel<<<N_RAYS / RPB, THREADS>>>(
        ray_start, ray_dir, depth, dists, sidx,
        W1, b1, w_sigma, W_rgb, W_dir, b_rgb, out);
}

// round 9
// speedup vs baseline: 1.5206x; 1.0551x over previous
#include <cuda_runtime.h>

#define N_RAYS   8192
#define N_SAMP   256
#define HID      64
#define OUT_ROW  261        // 3 colors + depth + missed + 256 probs
#define RPB      8          // rays per block (one warp per ray)
#define THREADS  256

__device__ __forceinline__ unsigned long long pack2(float lo, float hi) {
    unsigned long long r;
    asm("mov.b64 %0, {%1, %2};" : "=l"(r) : "f"(lo), "f"(hi));
    return r;
}
__device__ __forceinline__ void unpack2(unsigned long long v, float& lo, float& hi) {
    asm("mov.b64 {%0, %1}, %2;" : "=f"(lo), "=f"(hi) : "l"(v));
}
#define FMA2(acc, x, y) asm("fma.rn.f32x2 %0, %1, %2, %0;" : "+l"(acc) : "l"(x), "l"(y))

__global__ void __launch_bounds__(THREADS, 3)
volume_render_kernel(const float* __restrict__ ray_start,
                     const float* __restrict__ ray_dir,
                     const float* __restrict__ depth,
                     const float* __restrict__ dists,
                     const int*   __restrict__ sampled_idx,
                     const float* __restrict__ W1,
                     const float* __restrict__ b1,
                     const float* __restrict__ w_sigma,
                     const float* __restrict__ W_rgb,
                     const float* __restrict__ W_dir,
                     const float* __restrict__ b_rgb,
                     float* __restrict__ out)
{
    __shared__ ulonglong2 sAB[RPB][HID];  // .x=(a,a) .y=(b,b) per ray
    __shared__ ulonglong2 sWa[HID];       // .x=(ws,ws) .y=(wr0,wr0)
    __shared__ ulonglong2 sWb[HID];       // .x=(wr1,wr1) .y=(wr2,wr2)

    const int t    = threadIdx.x;
    const int rl   = t >> 5;      // warp id == ray slot
    const int lane = t & 31;
    const int r    = blockIdx.x * RPB + rl;

    const float rs0 = ray_start[3*r+0], rs1 = ray_start[3*r+1], rs2 = ray_start[3*r+2];
    const float rd0 = ray_dir  [3*r+0], rd1 = ray_dir  [3*r+1], rd2 = ray_dir  [3*r+2];

    // ---- prologue: per-ray affine coeffs + splatted weights ----
    #pragma unroll
    for (int q = 0; q < 2; q++) {
        int jj = lane + 32*q;
        float w0 = W1[jj], w1 = W1[HID + jj], w2 = W1[2*HID + jj];
        float a  = fmaf(rs2, w2, fmaf(rs1, w1, fmaf(rs0, w0, b1[jj])));
        float b  = fmaf(rd2, w2, fmaf(rd1, w1, rd0 * w0));
        sAB[rl][jj] = make_ulonglong2(pack2(a, a), pack2(b, b));
    }
    if (t < HID) {
        float ws = w_sigma[t];
        float q0 = W_rgb[3*t+0];
        float q1 = W_rgb[3*t+1];
        float q2 = W_rgb[3*t+2];
        sWa[t] = make_ulonglong2(pack2(ws, ws), pack2(q0, q0));
        sWb[t] = make_ulonglong2(pack2(q1, q1), pack2(q2, q2));
    }
    __syncthreads();

    // ---- load 8 depths per thread (dists/idx deferred past the MLP loop) ----
    const size_t si = (size_t)r * N_SAMP + lane * 8;
    const float4 dA = *(const float4*)(depth + si);
    const float4 dB = *(const float4*)(depth + si + 4);

    unsigned long long td[4];
    td[0] = pack2(dA.x, dA.y); td[1] = pack2(dA.z, dA.w);
    td[2] = pack2(dB.x, dB.y); td[3] = pack2(dB.z, dB.w);

    unsigned long long sg[4] = {0,0,0,0};
    unsigned long long a0[4] = {0,0,0,0};
    unsigned long long a1[4] = {0,0,0,0};
    unsigned long long a2[4] = {0,0,0,0};

    #pragma unroll 16
    for (int k = 0; k < HID; k++) {
        ulonglong2 ab = sAB[rl][k];   // broadcast LDS.128
        ulonglong2 wa = sWa[k];       // broadcast LDS.128
        ulonglong2 wb = sWb[k];       // broadcast LDS.128
        #pragma unroll
        for (int p = 0; p < 4; p++) {
            unsigned long long h;
            asm("fma.rn.f32x2 %0, %1, %2, %3;" : "=l"(h) : "l"(td[p]), "l"(ab.y), "l"(ab.x));
            float hlo, hhi;
            unpack2(h, hlo, hhi);
            hlo = fmaxf(hlo, 0.f);    // FMNMX — ALU pipe
            hhi = fmaxf(hhi, 0.f);    // FMNMX — ALU pipe
            unsigned long long pr = pack2(hlo, hhi);
            FMA2(sg[p], pr, wa.x);
            FMA2(a0[p], pr, wa.y);
            FMA2(a1[p], pr, wb.x);
            FMA2(a2[p], pr, wb.y);
        }
    }

    float sgv[8], c0v[8], c1v[8], c2v[8];
    #pragma unroll
    for (int p = 0; p < 4; p++) {
        unpack2(sg[p], sgv[2*p], sgv[2*p+1]);
        unpack2(a0[p], c0v[2*p], c0v[2*p+1]);
        unpack2(a1[p], c1v[2*p], c1v[2*p+1]);
        unpack2(a2[p], c2v[2*p], c2v[2*p+1]);
    }

    // ---- deferred loads ----
    const float4 xA = *(const float4*)(dists + si);
    const float4 xB = *(const float4*)(dists + si + 4);
    const int4   iA = *(const int4*)(sampled_idx + si);
    const int4   iB = *(const int4*)(sampled_idx + si + 4);

    const float ddv[8] = {xA.x,xA.y,xA.z,xA.w,xB.x,xB.y,xB.z,xB.w};
    const int   mkv[8] = {iA.x!=-1,iA.y!=-1,iA.z!=-1,iA.w!=-1,
                          iB.x!=-1,iB.y!=-1,iB.z!=-1,iB.w!=-1};

    // ---- free energy + local inclusive prefix cum[1..8] ----
    float cum[9];
    cum[0] = 0.f;
    #pragma unroll
    for (int k = 0; k < 8; k++) {
        float fe = mkv[k] ? fmaxf(sgv[k], 0.f) * ddv[k] * 7.0f : 0.f;
        cum[k+1] = cum[k] + fe;
    }
    const float run = cum[8];

    // warp-exclusive scan of per-thread totals
    float v = run;
    #pragma unroll
    for (int o = 1; o < 32; o <<= 1) {
        float n = __shfl_up_sync(0xffffffffu, v, o);
        if (lane >= o) v += n;
    }
    const float excl = v - run;

    // ---- per-ray view-dir color offsets ----
    const float dc0 = fmaf(rd2, W_dir[6], fmaf(rd1, W_dir[3], fmaf(rd0, W_dir[0], b_rgb[0])));
    const float dc1 = fmaf(rd2, W_dir[7], fmaf(rd1, W_dir[4], fmaf(rd0, W_dir[1], b_rgb[1])));
    const float dc2 = fmaf(rd2, W_dir[8], fmaf(rd1, W_dir[5], fmaf(rd0, W_dir[2], b_rgb[2])));

    // ---- transmittance via telescoping: prob[k] = E[k] - E[k+1] ----
    float E[9];
    #pragma unroll
    for (int k = 0; k < 9; k++)
        E[k] = __expf(-(excl + cum[k]));

    const float tdv[8] = {dA.x,dA.y,dA.z,dA.w,dB.x,dB.y,dB.z,dB.w};
    float* orow = out + (size_t)r * OUT_ROW;

    float s0 = 0.f, s1 = 0.f, s2 = 0.f, s3 = 0.f, s4 = 0.f;
    #pragma unroll
    for (int k = 0; k < 8; k++) {
        float prob = E[k] - E[k+1];
        float rr = __fdividef(1.f, 1.f + __expf(-(c0v[k] + dc0)));
        float gg = __fdividef(1.f, 1.f + __expf(-(c1v[k] + dc1)));
        float bb = __fdividef(1.f, 1.f + __expf(-(c2v[k] + dc2)));
        orow[5 + 8*lane + k] = prob;
        s0 += prob;
        s1 = fmaf(tdv[k], prob, s1);
        s2 = fmaf(rr,     prob, s2);
        s3 = fmaf(gg,     prob, s3);
        s4 = fmaf(bb,     prob, s4);
    }
    #pragma unroll
    for (int o = 16; o; o >>= 1) {
        s0 += __shfl_xor_sync(0xffffffffu, s0, o);
        s1 += __shfl_xor_sync(0xffffffffu, s1, o);
        s2 += __shfl_xor_sync(0xffffffffu, s2, o);
        s3 += __shfl_xor_sync(0xffffffffu, s3, o);
        s4 += __shfl_xor_sync(0xffffffffu, s4, o);
    }
    if (lane == 0) {
        orow[0] = s2;        // color r
        orow[1] = s3;        // color g
        orow[2] = s4;        // color b
        orow[3] = s1;        // depth
        orow[4] = 1.f - s0;  // missed
    }
}

extern "C" void kernel_launch(void* const* d_in, const int* in_sizes, int n_in,
                              void* d_out, int out_size)
{
    const float* ray_start = (const float*)d_in[0];
    const float* ray_dir   = (const float*)d_in[1];
    const float* depth     = (const float*)d_in[2];
    const float* dists     = (const float*)d_in[3];
    const int*   sidx      = (const int*)d_in[4];
    const float* W1        = (const float*)d_in[5];
    const float* b1        = (const float*)d_in[6];
    const float* w_sigma   = (const float*)d_in[7];
    const float* W_rgb     = (const float*)d_in[8];
    const float* W_dir     = (const float*)d_in[9];
    const float* b_rgb     = (const float*)d_in[10];
    float* out = (float*)d_out;

    volume_render_kernel<<<N_RAYS / RPB, THREADS>>>(
        ray_start, ray_dir, depth, dists, sidx,
        W1, b1, w_sigma, W_rgb, W_dir, b_rgb, out);
}

// round 10
// speedup vs baseline: 1.6079x; 1.0574x over previous
#include <cuda_runtime.h>

#define N_RAYS   8192
#define N_SAMP   256
#define HID      64
#define OUT_ROW  261        // 3 colors + depth + missed + 256 probs
#define RPB      2          // rays per block (one warp per ray)
#define THREADS  64

__device__ __forceinline__ unsigned long long pack2(float lo, float hi) {
    unsigned long long r;
    asm("mov.b64 %0, {%1, %2};" : "=l"(r) : "f"(lo), "f"(hi));
    return r;
}
__device__ __forceinline__ void unpack2(unsigned long long v, float& lo, float& hi) {
    asm("mov.b64 {%0, %1}, %2;" : "=f"(lo), "=f"(hi) : "l"(v));
}
#define FMA2(acc, x, y) asm("fma.rn.f32x2 %0, %1, %2, %0;" : "+l"(acc) : "l"(x), "l"(y))

__device__ __forceinline__ float fast_sigmoid(float x) {
    float th;
    asm("tanh.approx.f32 %0, %1;" : "=f"(th) : "f"(0.5f * x));
    return fmaf(0.5f, th, 0.5f);
}

__global__ void __launch_bounds__(THREADS, 12)
volume_render_kernel(const float* __restrict__ ray_start,
                     const float* __restrict__ ray_dir,
                     const float* __restrict__ depth,
                     const float* __restrict__ dists,
                     const int*   __restrict__ sampled_idx,
                     const float* __restrict__ W1,
                     const float* __restrict__ b1,
                     const float* __restrict__ w_sigma,
                     const float* __restrict__ W_rgb,
                     const float* __restrict__ W_dir,
                     const float* __restrict__ b_rgb,
                     float* __restrict__ out)
{
    __shared__ ulonglong2 sAB[RPB][HID];  // .x=(a,a) .y=(b,b) per ray
    __shared__ ulonglong2 sWa[HID];       // .x=(ws,ws) .y=(wr0,wr0)
    __shared__ ulonglong2 sWb[HID];       // .x=(wr1,wr1) .y=(wr2,wr2)

    const int t    = threadIdx.x;
    const int rl   = t >> 5;      // warp id == ray slot (0..1)
    const int lane = t & 31;
    const int r    = blockIdx.x * RPB + rl;

    const float rs0 = ray_start[3*r+0], rs1 = ray_start[3*r+1], rs2 = ray_start[3*r+2];
    const float rd0 = ray_dir  [3*r+0], rd1 = ray_dir  [3*r+1], rd2 = ray_dir  [3*r+2];

    // ---- prologue: per-ray affine coeffs + splatted weights ----
    #pragma unroll
    for (int q = 0; q < 2; q++) {
        int jj = lane + 32*q;
        float w0 = W1[jj], w1 = W1[HID + jj], w2 = W1[2*HID + jj];
        float a  = fmaf(rs2, w2, fmaf(rs1, w1, fmaf(rs0, w0, b1[jj])));
        float b  = fmaf(rd2, w2, fmaf(rd1, w1, rd0 * w0));
        sAB[rl][jj] = make_ulonglong2(pack2(a, a), pack2(b, b));
    }
    {
        int jj = t;               // 64 threads cover HID exactly
        float ws = w_sigma[jj];
        float q0 = W_rgb[3*jj+0];
        float q1 = W_rgb[3*jj+1];
        float q2 = W_rgb[3*jj+2];
        sWa[jj] = make_ulonglong2(pack2(ws, ws), pack2(q0, q0));
        sWb[jj] = make_ulonglong2(pack2(q1, q1), pack2(q2, q2));
    }
    __syncthreads();

    // ---- load 8 depths per thread ----
    const size_t si = (size_t)r * N_SAMP + lane * 8;
    const float4 dA = *(const float4*)(depth + si);
    const float4 dB = *(const float4*)(depth + si + 4);

    unsigned long long td[4];
    td[0] = pack2(dA.x, dA.y); td[1] = pack2(dA.z, dA.w);
    td[2] = pack2(dB.x, dB.y); td[3] = pack2(dB.z, dB.w);

    unsigned long long sg[4] = {0,0,0,0};
    unsigned long long a0[4] = {0,0,0,0};
    unsigned long long a1[4] = {0,0,0,0};
    unsigned long long a2[4] = {0,0,0,0};

    #define K_BODY(k)                                                              \
    {                                                                              \
        ulonglong2 ab = sAB[rl][k];                                                \
        ulonglong2 wa = sWa[k];                                                    \
        ulonglong2 wb = sWb[k];                                                    \
        _Pragma("unroll")                                                          \
        for (int p = 0; p < 4; p++) {                                              \
            unsigned long long h;                                                  \
            asm("fma.rn.f32x2 %0, %1, %2, %3;"                                     \
                : "=l"(h) : "l"(td[p]), "l"(ab.y), "l"(ab.x));                     \
            float hlo, hhi;                                                        \
            unpack2(h, hlo, hhi);                                                  \
            hlo = fmaxf(hlo, 0.f);                                                 \
            hhi = fmaxf(hhi, 0.f);                                                 \
            unsigned long long pr = pack2(hlo, hhi);                               \
            FMA2(sg[p], pr, wa.x);                                                 \
            FMA2(a0[p], pr, wa.y);                                                 \
            FMA2(a1[p], pr, wb.x);                                                 \
            FMA2(a2[p], pr, wb.y);                                                 \
        }                                                                          \
    }

    // first 48 hidden units
    #pragma unroll 16
    for (int k = 0; k < 48; k++) K_BODY(k)

    // prefetch epilogue inputs — latency hidden behind last 16 iterations
    const float4 xA = *(const float4*)(dists + si);
    const float4 xB = *(const float4*)(dists + si + 4);
    const int4   iA = *(const int4*)(sampled_idx + si);
    const int4   iB = *(const int4*)(sampled_idx + si + 4);

    #pragma unroll 16
    for (int k = 48; k < HID; k++) K_BODY(k)
    #undef K_BODY

    float sgv[8], c0v[8], c1v[8], c2v[8];
    #pragma unroll
    for (int p = 0; p < 4; p++) {
        unpack2(sg[p], sgv[2*p], sgv[2*p+1]);
        unpack2(a0[p], c0v[2*p], c0v[2*p+1]);
        unpack2(a1[p], c1v[2*p], c1v[2*p+1]);
        unpack2(a2[p], c2v[2*p], c2v[2*p+1]);
    }

    const float ddv[8] = {xA.x,xA.y,xA.z,xA.w,xB.x,xB.y,xB.z,xB.w};
    const int   mkv[8] = {iA.x!=-1,iA.y!=-1,iA.z!=-1,iA.w!=-1,
                          iB.x!=-1,iB.y!=-1,iB.z!=-1,iB.w!=-1};

    // ---- free energy + local inclusive prefix cum[1..8] ----
    float cum[9];
    cum[0] = 0.f;
    #pragma unroll
    for (int k = 0; k < 8; k++) {
        float fe = mkv[k] ? fmaxf(sgv[k], 0.f) * ddv[k] * 7.0f : 0.f;
        cum[k+1] = cum[k] + fe;
    }
    const float run = cum[8];

    // warp-exclusive scan of per-thread totals
    float v = run;
    #pragma unroll
    for (int o = 1; o < 32; o <<= 1) {
        float n = __shfl_up_sync(0xffffffffu, v, o);
        if (lane >= o) v += n;
    }
    const float excl = v - run;

    // ---- per-ray view-dir color offsets ----
    const float dc0 = fmaf(rd2, W_dir[6], fmaf(rd1, W_dir[3], fmaf(rd0, W_dir[0], b_rgb[0])));
    const float dc1 = fmaf(rd2, W_dir[7], fmaf(rd1, W_dir[4], fmaf(rd0, W_dir[1], b_rgb[1])));
    const float dc2 = fmaf(rd2, W_dir[8], fmaf(rd1, W_dir[5], fmaf(rd0, W_dir[2], b_rgb[2])));

    // ---- transmittance via telescoping: prob[k] = E[k] - E[k+1] ----
    float E[9];
    #pragma unroll
    for (int k = 0; k < 9; k++)
        E[k] = __expf(-(excl + cum[k]));

    const float tdv[8] = {dA.x,dA.y,dA.z,dA.w,dB.x,dB.y,dB.z,dB.w};
    float* orow = out + (size_t)r * OUT_ROW;

    float s0 = 0.f, s1 = 0.f, s2 = 0.f, s3 = 0.f, s4 = 0.f;
    #pragma unroll
    for (int k = 0; k < 8; k++) {
        float prob = E[k] - E[k+1];
        float rr = fast_sigmoid(c0v[k] + dc0);
        float gg = fast_sigmoid(c1v[k] + dc1);
        float bb = fast_sigmoid(c2v[k] + dc2);
        orow[5 + 8*lane + k] = prob;
        s0 += prob;
        s1 = fmaf(tdv[k], prob, s1);
        s2 = fmaf(rr,     prob, s2);
        s3 = fmaf(gg,     prob, s3);
        s4 = fmaf(bb,     prob, s4);
    }
    #pragma unroll
    for (int o = 16; o; o >>= 1) {
        s0 += __shfl_xor_sync(0xffffffffu, s0, o);
        s1 += __shfl_xor_sync(0xffffffffu, s1, o);
        s2 += __shfl_xor_sync(0xffffffffu, s2, o);
        s3 += __shfl_xor_sync(0xffffffffu, s3, o);
        s4 += __shfl_xor_sync(0xffffffffu, s4, o);
    }
    if (lane == 0) {
        orow[0] = s2;        // color r
        orow[1] = s3;        // color g
        orow[2] = s4;        // color b
        orow[3] = s1;        // depth
        orow[4] = 1.f - s0;  // missed
    }
}

extern "C" void kernel_launch(void* const* d_in, const int* in_sizes, int n_in,
                              void* d_out, int out_size)
{
    const float* ray_start = (const float*)d_in[0];
    const float* ray_dir   = (const float*)d_in[1];
    const float* depth     = (const float*)d_in[2];
    const float* dists     = (const float*)d_in[3];
    const int*   sidx      = (const int*)d_in[4];
    const float* W1        = (const float*)d_in[5];
    const float* b1        = (const float*)d_in[6];
    const float* w_sigma   = (const float*)d_in[7];
    const float* W_rgb     = (const float*)d_in[8];
    const float* W_dir     = (const float*)d_in[9];
    const float* b_rgb     = (const float*)d_in[10];
    float* out = (float*)d_out;

    volume_render_kernel<<<N_RAYS / RPB, THREADS>>>(
        ray_start, ray_dir, depth, dists, sidx,
        W1, b1, w_sigma, W_rgb, W_dir, b_rgb, out);
}